// round 2
// baseline (speedup 1.0000x reference)
#include <cuda_runtime.h>
#include <math.h>

#define KB_B 32
#define KB_C 256
#define KB_G 8
#define KB_CG 32
#define KB_H 56
#define KB_W 56
#define KB_P 3136
#define KB_BG 256
#define KB_NCH 8192   // B*C = BG*CG
#define KB_EPS 1e-5f

// ---------------- scratch (static device globals; no allocations) ----------------
__device__ float g_rowS[KB_NCH * KB_H];
__device__ float g_colS[KB_NCH * KB_W];
__device__ float g_S9[KB_NCH * 9];
__device__ float g_sh[KB_NCH * KB_H];    // sigmoid(row gate)
__device__ float g_sw[KB_NCH * KB_W];    // sigmoid(col gate)
__device__ float g_mu[KB_NCH];           // per-(b,c) spatial mean of x0
__device__ float g_m2[KB_NCH];           // per-(b,c) spatial mean of x0^2
__device__ float g_w1c[KB_NCH];          // x21*gn_w*isig per channel
__device__ float g_c1[KB_BG];            // per-bg constant for weights1
__device__ float g_alpha[KB_C];          // isbn/C
__device__ float g_bm[KB_C];
__device__ float g_isbn[KB_C];
__device__ float g_veff[KB_CG * 9];      // x11-folded w3a
__device__ float g_wmean[KB_C * 9];      // out-channel mean of w3b
__device__ float g_cx11b;                // x11 . b3a
__device__ float g_z9[(size_t)KB_B * 9 * KB_P];
__device__ float g_t3[KB_B * KB_P];      // x31 logits
__device__ float g_x31[KB_B * KB_P];
__device__ float g_x41[KB_B * KB_P];
__device__ float g_w1map[(size_t)KB_BG * KB_P];  // sigmoid(weights1)
__device__ float g_s1[KB_B * KB_C * 9];
__device__ float g_t41[KB_NCH];          // sum_p x41*x0
__device__ float g_w2sig[KB_NCH];        // sigmoid(weights2)

__device__ __forceinline__ float warpSum(float v) {
#pragma unroll
    for (int o = 16; o; o >>= 1) v += __shfl_xor_sync(0xffffffffu, v, o);
    return v;
}
__device__ __forceinline__ float warpMax(float v) {
#pragma unroll
    for (int o = 16; o; o >>= 1) v = fmaxf(v, __shfl_xor_sync(0xffffffffu, v, o));
    return v;
}
__device__ __forceinline__ float sigm(float v) { return 1.0f / (1.0f + expf(-v)); }

// ---------------- prep: wmean[c,k] = mean over out-channel of w3b ----------------
__global__ void kPrepW(const float* __restrict__ w3b) {
    int t = blockIdx.x * blockDim.x + threadIdx.x;
    if (t >= KB_C * 9) return;
    float s = 0.f;
    for (int o = 0; o < KB_C; o++) s += w3b[(size_t)o * (KB_C * 9) + t];
    g_wmean[t] = s * (1.0f / KB_C);
}

// ---- prep: x11 = softmax(gn_b); veff = x11 . w3a; cx11b = x11 . b3a ----
__global__ void kPrepV(const float* __restrict__ w3a, const float* __restrict__ b3a,
                       const float* __restrict__ gnb) {
    __shared__ float x11s[KB_CG];
    int t = threadIdx.x;  // 288 threads
    if (t < KB_CG) {
        float v = gnb[t];
        float mx = warpMax(v);
        float e = expf(v - mx);
        float s = warpSum(e);
        x11s[t] = e / s;
    }
    __syncthreads();
    if (t < KB_CG * 9) {
        float s = 0.f;
        for (int c = 0; c < KB_CG; c++) s += x11s[c] * w3a[c * (KB_CG * 9) + t];
        g_veff[t] = s;
    }
    if (t == 0) {
        float s = 0.f;
        for (int c = 0; c < KB_CG; c++) s += x11s[c] * b3a[c];
        g_cx11b = s;
    }
}

// ---- kA: per channel row/col sums + 9 shifted-window sums S9 ----
__global__ __launch_bounds__(256) void kA(const float* __restrict__ x) {
    int n = blockIdx.x;  // flat channel = b*C + c
    __shared__ float sm[KB_P];
    __shared__ float srow[KB_H], scol[KB_W];
    const float* xc = x + (size_t)n * KB_P;
    for (int p = threadIdx.x; p < KB_P; p += 256) sm[p] = xc[p];
    __syncthreads();
    int t = threadIdx.x;
    if (t < KB_H) {
        float s = 0.f;
        for (int j = 0; j < KB_W; j++) s += sm[t * KB_W + j];
        srow[t] = s;
        g_rowS[n * KB_H + t] = s;
    } else if (t < KB_H + KB_W) {
        int j = t - KB_H;
        float s = 0.f;
        for (int i = 0; i < KB_H; i++) s += sm[i * KB_W + j];
        scol[j] = s;
        g_colS[n * KB_W + j] = s;
    }
    __syncthreads();
    if (t == 0) {
        float tot = 0.f;
        for (int i = 0; i < KB_H; i++) tot += srow[i];
        for (int dy = 0; dy < 3; dy++)
            for (int dx = 0; dx < 3; dx++) {
                float s = tot;
                int ie = -1, je = -1;
                if (dy == 0) { s -= srow[KB_H - 1]; ie = KB_H - 1; }
                else if (dy == 2) { s -= srow[0]; ie = 0; }
                if (dx == 0) { s -= scol[KB_W - 1]; je = KB_W - 1; }
                else if (dx == 2) { s -= scol[0]; je = 0; }
                if (ie >= 0 && je >= 0) s += sm[ie * KB_W + je];
                g_S9[n * 9 + dy * 3 + dx] = s;
            }
    }
}

// ---- kB: 1x1 conv (32x32 over 112 positions) + sigmoid -> sh, sw ----
__global__ __launch_bounds__(128) void kB(const float* __restrict__ w1, const float* __restrict__ b1) {
    int bg = blockIdx.x;
    __shared__ float cat[KB_CG][112];
    __shared__ float w1s[KB_CG * KB_CG];
    int t = threadIdx.x;
    for (int m = t; m < KB_CG * KB_CG; m += 128) w1s[m] = w1[m];
    for (int m = t; m < KB_CG * 112; m += 128) {
        int cc = m / 112, u = m % 112;
        int n = bg * KB_CG + cc;
        cat[cc][u] = (u < KB_H) ? g_rowS[n * KB_H + u] * (1.0f / KB_W)
                                : g_colS[n * KB_W + (u - KB_H)] * (1.0f / KB_H);
    }
    __syncthreads();
    for (int m = t; m < KB_CG * 112; m += 128) {
        int o = m / 112, u = m % 112;
        float acc = b1[o];
        for (int i = 0; i < KB_CG; i++) acc += w1s[o * KB_CG + i] * cat[i][u];
        float s = sigm(acc);
        int n = bg * KB_CG + o;
        if (u < KB_H) g_sh[n * KB_H + u] = s;
        else g_sw[n * KB_W + (u - KB_H)] = s;
    }
}

// ---- kC: per-channel mean / mean-of-squares of x0 = x * sh * sw ----
__global__ __launch_bounds__(256) void kC(const float* __restrict__ x) {
    int n = blockIdx.x;
    __shared__ float shs[KB_H], sws[KB_W];
    __shared__ float red[16];
    int t = threadIdx.x;
    if (t < KB_H) shs[t] = g_sh[n * KB_H + t];
    else if (t < KB_H + KB_W) sws[t - KB_H] = g_sw[n * KB_W + (t - KB_H)];
    __syncthreads();
    const float* xc = x + (size_t)n * KB_P;
    float s = 0.f, s2 = 0.f;
    for (int p = t; p < KB_P; p += 256) {
        int i = p / KB_W, j = p - i * KB_W;
        float v = xc[p] * shs[i] * sws[j];
        s += v;
        s2 += v * v;
    }
    s = warpSum(s);
    s2 = warpSum(s2);
    int wid = t >> 5, lane = t & 31;
    if (lane == 0) { red[wid] = s; red[8 + wid] = s2; }
    __syncthreads();
    if (t == 0) {
        float a = 0.f, b2 = 0.f;
        for (int k = 0; k < 8; k++) { a += red[k]; b2 += red[8 + k]; }
        g_mu[n] = a * (1.0f / KB_P);
        g_m2[n] = b2 * (1.0f / KB_P);
    }
}

// ---- kD1: per bg: x2mean from S9, x21 softmax, fold GN coeffs ----
__global__ __launch_bounds__(32) void kD1(const float* __restrict__ w3a, const float* __restrict__ b3a,
                                          const float* __restrict__ gnw, const float* __restrict__ gnb) {
    int bg = blockIdx.x;
    int c = threadIdx.x;  // 32 threads = 1 warp
    __shared__ float S9s[KB_CG * 9];
    for (int m = c; m < KB_CG * 9; m += 32) S9s[m] = g_S9[bg * KB_CG * 9 + m];
    __syncwarp();
    float acc = 0.f;
    for (int m = 0; m < KB_CG * 9; m++) acc += w3a[c * KB_CG * 9 + m] * S9s[m];
    float x2m = acc * (1.0f / KB_P) + b3a[c];
    float mx = warpMax(x2m);
    float e = expf(x2m - mx);
    float ssum = warpSum(e);
    float x21 = e / ssum;
    int n = bg * KB_CG + c;
    float mu = g_mu[n];
    float var = g_m2[n] - mu * mu;
    if (var < 0.f) var = 0.f;
    float isig = rsqrtf(var + KB_EPS);
    g_w1c[n] = x21 * gnw[c] * isig;
    float part = x21 * (gnb[c] - gnw[c] * mu * isig);
    part = warpSum(part);
    if (c == 0) g_c1[bg] = part + g_cx11b;
}

// ---- kD2: per-channel batchnorm stats over (b,h,w) ----
__global__ __launch_bounds__(256) void kD2() {
    int c = threadIdx.x;
    float s = 0.f, s2 = 0.f;
    for (int b = 0; b < KB_B; b++) { s += g_mu[b * KB_C + c]; s2 += g_m2[b * KB_C + c]; }
    s *= (1.0f / KB_B);
    s2 *= (1.0f / KB_B);
    float bv = s2 - s * s;
    if (bv < 0.f) bv = 0.f;
    float isbn = rsqrtf(bv + KB_EPS);
    g_bm[c] = s;
    g_isbn[c] = isbn;
    g_alpha[c] = isbn * (1.0f / KB_C);
}

// ---- kE: fused channel sweep: t3 logits, z9 (for x4mean), weights1 map ----
__global__ __launch_bounds__(448) void kE(const float* __restrict__ x) {
    int tile = blockIdx.x, b = blockIdx.y;
    int i0 = tile * 8;
    __shared__ float smt[4][580];    // 4 channels, 10x58 halo tile each
    __shared__ float wms[KB_C * 9];
    __shared__ float vfs[KB_CG * 9];
    __shared__ float als[KB_C];
    __shared__ float wcs[KB_C];
    int t = threadIdx.x;  // 448 = 8 rows x 56 cols
    for (int m = t; m < KB_C * 9; m += 448) wms[m] = g_wmean[m];
    for (int m = t; m < KB_CG * 9; m += 448) vfs[m] = g_veff[m];
    for (int m = t; m < KB_C; m += 448) { als[m] = g_alpha[m]; wcs[m] = g_w1c[b * KB_C + m]; }
    int r = t / 56, j = t - r * 56;
    int i = i0 + r;
    const float* xb = x + (size_t)b * KB_C * KB_P;
    float t3a = 0.f;
    float z[9];
#pragma unroll
    for (int k = 0; k < 9; k++) z[k] = 0.f;
    for (int g = 0; g < KB_G; g++) {
        float cp = 0.f, wp = 0.f;
        for (int cc0 = 0; cc0 < KB_CG; cc0 += 4) {
            __syncthreads();
            for (int m = t; m < 4 * 580; m += 448) {
                int q = m / 580, mm = m - q * 580;
                int rr = mm / 58, cl = mm - rr * 58;
                int gi = i0 + rr - 1, gj = cl - 1;
                int c = g * KB_CG + cc0 + q;
                smt[q][mm] = (gi >= 0 && gi < KB_H && gj >= 0 && gj < KB_W)
                                 ? xb[(size_t)c * KB_P + gi * KB_W + gj] : 0.f;
            }
            __syncthreads();
#pragma unroll
            for (int q = 0; q < 4; q++) {
                int cc = cc0 + q;
                int c = g * KB_CG + cc;
                const float* sp = smt[q];
                float xv = sp[(r + 1) * 58 + (j + 1)];
                float x0 = xv * g_sh[(b * KB_C + c) * KB_H + i] * g_sw[(b * KB_C + c) * KB_W + j];
                t3a += als[c] * x0;
                wp += wcs[c] * x0;
#pragma unroll
                for (int k = 0; k < 9; k++) z[k] += wms[c * 9 + k] * xv;
#pragma unroll
                for (int dy = 0; dy < 3; dy++)
#pragma unroll
                    for (int dx = 0; dx < 3; dx++)
                        cp += vfs[cc * 9 + dy * 3 + dx] * sp[(r + dy) * 58 + (j + dx)];
            }
        }
        int bg = b * KB_G + g;
        g_w1map[(size_t)bg * KB_P + i * KB_W + j] = sigm(cp + wp + g_c1[bg]);
    }
    int p = i * KB_W + j;
    g_t3[b * KB_P + p] = t3a;
#pragma unroll
    for (int k = 0; k < 9; k++) g_z9[((size_t)(b * 9 + k)) * KB_P + p] = z[k];
}

// ---- kSoft31: x31 = softmax over pixels of t3 ----
__global__ __launch_bounds__(512) void kSoft31() {
    int b = blockIdx.x;
    __shared__ float buf[KB_P];
    __shared__ float red[17];
    int t = threadIdx.x;
    float lm = -3.4e38f;
    for (int p = t; p < KB_P; p += 512) {
        float v = g_t3[b * KB_P + p];
        buf[p] = v;
        lm = fmaxf(lm, v);
    }
    lm = warpMax(lm);
    int wid = t >> 5, lane = t & 31;
    if (lane == 0) red[wid] = lm;
    __syncthreads();
    if (t < 32) {
        float v = (t < 16) ? red[t] : -3.4e38f;
        v = warpMax(v);
        if (t == 0) red[16] = v;
    }
    __syncthreads();
    float mx = red[16];
    float ls = 0.f;
    for (int p = t; p < KB_P; p += 512) {
        float e = expf(buf[p] - mx);
        buf[p] = e;
        ls += e;
    }
    ls = warpSum(ls);
    __syncthreads();
    if (lane == 0) red[wid] = ls;
    __syncthreads();
    if (t < 32) {
        float v = (t < 16) ? red[t] : 0.f;
        v = warpSum(v);
        if (t == 0) red[16] = v;
    }
    __syncthreads();
    float inv = 1.0f / red[16];
    for (int p = t; p < KB_P; p += 512) g_x31[b * KB_P + p] = buf[p] * inv;
}

// ---- kSoft41: x4mean via 9-shift combine of z9; x41 = pixel softmax ----
__global__ __launch_bounds__(512) void kSoft41() {
    int b = blockIdx.x;
    __shared__ float buf[KB_P];
    __shared__ float red[17];
    int t = threadIdx.x;
    float lm = -3.4e38f;
    for (int p = t; p < KB_P; p += 512) {
        int i = p / KB_W, j = p - i * KB_W;
        float s = 0.f;
#pragma unroll
        for (int dy = 0; dy < 3; dy++) {
            int gi = i + dy - 1;
            if (gi < 0 || gi >= KB_H) continue;
#pragma unroll
            for (int dx = 0; dx < 3; dx++) {
                int gj = j + dx - 1;
                if (gj < 0 || gj >= KB_W) continue;
                s += g_z9[((size_t)(b * 9 + dy * 3 + dx)) * KB_P + gi * KB_W + gj];
            }
        }
        buf[p] = s;
        lm = fmaxf(lm, s);
    }
    lm = warpMax(lm);
    int wid = t >> 5, lane = t & 31;
    if (lane == 0) red[wid] = lm;
    __syncthreads();
    if (t < 32) {
        float v = (t < 16) ? red[t] : -3.4e38f;
        v = warpMax(v);
        if (t == 0) red[16] = v;
    }
    __syncthreads();
    float mx = red[16];
    float ls = 0.f;
    for (int p = t; p < KB_P; p += 512) {
        float e = expf(buf[p] - mx);
        buf[p] = e;
        ls += e;
    }
    ls = warpSum(ls);
    __syncthreads();
    if (lane == 0) red[wid] = ls;
    __syncthreads();
    if (t < 32) {
        float v = (t < 16) ? red[t] : 0.f;
        v = warpSum(v);
        if (t == 0) red[16] = v;
    }
    __syncthreads();
    float inv = 1.0f / red[16];
    for (int p = t; p < KB_P; p += 512) g_x41[b * KB_P + p] = buf[p] * inv;
}

// ---- kF: per-(b,c) pass: s1[k] = sum_q x31[q-off(k)]*x[q]; t41 = sum x41*x0 ----
__global__ __launch_bounds__(256) void kF(const float* __restrict__ x) {
    int n = blockIdx.x;  // b*C + c
    int b = n >> 8;
    __shared__ float x31s[KB_P];
    __shared__ float x41s[KB_P];
    __shared__ float shs[KB_H], sws[KB_W];
    __shared__ float red[10 * 8];
    int t = threadIdx.x;
    for (int p = t; p < KB_P; p += 256) {
        x31s[p] = g_x31[b * KB_P + p];
        x41s[p] = g_x41[b * KB_P + p];
    }
    if (t < KB_H) shs[t] = g_sh[n * KB_H + t];
    else if (t < KB_H + KB_W) sws[t - KB_H] = g_sw[n * KB_W + (t - KB_H)];
    __syncthreads();
    const float* xc = x + (size_t)n * KB_P;
    float acc[9];
#pragma unroll
    for (int k = 0; k < 9; k++) acc[k] = 0.f;
    float t41 = 0.f;
    for (int p = t; p < KB_P; p += 256) {
        int i = p / KB_W, j = p - i * KB_W;
        float xv = xc[p];
        float x0 = xv * shs[i] * sws[j];
        t41 += x41s[p] * x0;
#pragma unroll
        for (int dy = 0; dy < 3; dy++) {
            int pi = i - (dy - 1);
            if (pi < 0 || pi >= KB_H) continue;
#pragma unroll
            for (int dx = 0; dx < 3; dx++) {
                int pj = j - (dx - 1);
                if (pj < 0 || pj >= KB_W) continue;
                acc[dy * 3 + dx] += x31s[pi * KB_W + pj] * xv;
            }
        }
    }
    int wid = t >> 5, lane = t & 31;
#pragma unroll
    for (int k = 0; k < 9; k++) {
        acc[k] = warpSum(acc[k]);
        if (lane == 0) red[wid * 10 + k] = acc[k];
    }
    t41 = warpSum(t41);
    if (lane == 0) red[wid * 10 + 9] = t41;
    __syncthreads();
    if (t < 10) {
        float s = 0.f;
        for (int w = 0; w < 8; w++) s += red[w * 10 + t];
        if (t < 9) g_s1[n * 9 + t] = s;
        else g_t41[n] = s;
    }
}

// ---- kW2: weights2 = w3b . s1 + b3b + isbn*(t41 - bm); sigmoid ----
__global__ __launch_bounds__(256) void kW2(const float* __restrict__ w3b, const float* __restrict__ b3b) {
    int b = blockIdx.x;
    __shared__ float s1s[KB_C * 9];
    int t = threadIdx.x;
    for (int m = t; m < KB_C * 9; m += 256) s1s[m] = g_s1[b * KB_C * 9 + m];
    __syncthreads();
    int wid = t >> 5, lane = t & 31;
    for (int c = wid; c < KB_C; c += 8) {
        float a = 0.f;
        for (int m = lane; m < KB_C * 9; m += 32) a += w3b[(size_t)c * (KB_C * 9) + m] * s1s[m];
        a = warpSum(a);
        if (lane == 0) {
            float w2 = a + b3b[c] + g_isbn[c] * (g_t41[b * KB_C + c] - g_bm[c]);
            g_w2sig[b * KB_C + c] = sigm(w2);
        }
    }
}

// ---- kFinal: out = x * (sigmoid(w1map) + sigmoid(w2)) ----
__global__ __launch_bounds__(256) void kFinal(const float* __restrict__ x, float* __restrict__ out) {
    size_t e = (size_t)blockIdx.x * 256 + threadIdx.x;  // float4 index
    const size_t total = (size_t)KB_B * KB_C * (KB_P / 4);
    if (e >= total) return;
    int n = (int)(e / (KB_P / 4));
    int p4 = (int)(e % (KB_P / 4));
    int bg = n >> 5;  // (b*256+c)/32 = b*8 + c/32
    float4 xv = ((const float4*)x)[e];
    float4 wm = ((const float4*)g_w1map)[(size_t)bg * (KB_P / 4) + p4];
    float w2 = g_w2sig[n];
    float4 o;
    o.x = xv.x * (wm.x + w2);
    o.y = xv.y * (wm.y + w2);
    o.z = xv.z * (wm.z + w2);
    o.w = xv.w * (wm.w + w2);
    ((float4*)out)[e] = o;
}

extern "C" void kernel_launch(void* const* d_in, const int* in_sizes, int n_in,
                              void* d_out, int out_size) {
    const float* x   = (const float*)d_in[0];
    const float* w1  = (const float*)d_in[1];
    const float* b1  = (const float*)d_in[2];
    const float* w3a = (const float*)d_in[3];
    const float* b3a = (const float*)d_in[4];
    const float* w3b = (const float*)d_in[5];
    const float* b3b = (const float*)d_in[6];
    const float* gnw = (const float*)d_in[7];
    const float* gnb = (const float*)d_in[8];
    float* out = (float*)d_out;

    kPrepW<<<(KB_C * 9 + 255) / 256, 256>>>(w3b);
    kPrepV<<<1, 288>>>(w3a, b3a, gnb);
    kA<<<KB_NCH, 256>>>(x);
    kB<<<KB_BG, 128>>>(w1, b1);
    kC<<<KB_NCH, 256>>>(x);
    kD1<<<KB_BG, 32>>>(w3a, b3a, gnw, gnb);
    kD2<<<1, 256>>>();
    kE<<<dim3(7, KB_B), 448>>>(x);
    kSoft31<<<KB_B, 512>>>();
    kSoft41<<<KB_B, 512>>>();
    kF<<<KB_NCH, 256>>>(x);
    kW2<<<KB_B, 256>>>(w3b, b3b);
    size_t total4 = (size_t)KB_B * KB_C * (KB_P / 4);
    kFinal<<<(unsigned)((total4 + 255) / 256), 256>>>(x, out);
}

// round 3
// speedup vs baseline: 1.6581x; 1.6581x over previous
#include <cuda_runtime.h>
#include <math.h>

#define KB_B 32
#define KB_C 256
#define KB_G 8
#define KB_CG 32
#define KB_H 56
#define KB_W 56
#define KB_P 3136
#define KB_BG 256
#define KB_NCH 8192   // B*C
#define KB_EPS 1e-5f

// ---------------- scratch ----------------
__device__ float g_rowS[KB_NCH * KB_H];
__device__ float g_colS[KB_NCH * KB_W];
__device__ float g_S9[KB_NCH * 9];
__device__ float g_sh[KB_NCH * KB_H];
__device__ float g_sw[KB_NCH * KB_W];
__device__ float g_mu[KB_NCH];
__device__ float g_m2[KB_NCH];
__device__ float g_w1c[KB_NCH];
__device__ float g_c1[KB_BG];
__device__ float g_alpha[KB_C];
__device__ float g_bm[KB_C];
__device__ float g_isbn[KB_C];
__device__ float g_veff[KB_CG * 9];
__device__ float g_wmean[KB_C * 9];
__device__ float g_cx11b;
__device__ float g_z9[(size_t)KB_B * 9 * KB_P];
__device__ float g_t3[KB_B * KB_P];
__device__ float g_x31[KB_B * KB_P];
__device__ float g_x41[KB_B * KB_P];
__device__ float g_w1map[(size_t)KB_BG * KB_P];
__device__ float g_s1[KB_B * KB_C * 9];
__device__ float g_t41[KB_NCH];
__device__ float g_w2sig[KB_NCH];

__device__ __forceinline__ float warpSum(float v) {
#pragma unroll
    for (int o = 16; o; o >>= 1) v += __shfl_xor_sync(0xffffffffu, v, o);
    return v;
}
__device__ __forceinline__ float warpMax(float v) {
#pragma unroll
    for (int o = 16; o; o >>= 1) v = fmaxf(v, __shfl_xor_sync(0xffffffffu, v, o));
    return v;
}
__device__ __forceinline__ float sigm(float v) { return 1.0f / (1.0f + expf(-v)); }

// ---- prep: wmean[c,k] = out-channel mean of w3b ----
__global__ void kPrepW(const float* __restrict__ w3b) {
    int t = blockIdx.x * blockDim.x + threadIdx.x;
    if (t >= KB_C * 9) return;
    float s = 0.f;
    for (int o = 0; o < KB_C; o++) s += w3b[(size_t)o * (KB_C * 9) + t];
    g_wmean[t] = s * (1.0f / KB_C);
}

// ---- prep: x11 = softmax(gn_b); veff = x11 . w3a; cx11b = x11 . b3a ----
__global__ void kPrepV(const float* __restrict__ w3a, const float* __restrict__ b3a,
                       const float* __restrict__ gnb) {
    __shared__ float x11s[KB_CG];
    int t = threadIdx.x;  // 288
    if (t < KB_CG) {
        float v = gnb[t];
        float mx = warpMax(v);
        float e = expf(v - mx);
        float s = warpSum(e);
        x11s[t] = e / s;
    }
    __syncthreads();
    if (t < KB_CG * 9) {
        float s = 0.f;
        for (int c = 0; c < KB_CG; c++) s += x11s[c] * w3a[c * (KB_CG * 9) + t];
        g_veff[t] = s;
    }
    if (t == 0) {
        float s = 0.f;
        for (int c = 0; c < KB_CG; c++) s += x11s[c] * b3a[c];
        g_cx11b = s;
    }
}

// ---- kA: per-channel row/col sums + shifted window sums S9 ----
__global__ __launch_bounds__(256) void kA(const float* __restrict__ x) {
    int n = blockIdx.x;
    __shared__ float sm[KB_P];
    __shared__ float srow[KB_H], scol[KB_W];
    const float4* xc = (const float4*)(x + (size_t)n * KB_P);
    for (int p4 = threadIdx.x; p4 < KB_P / 4; p4 += 256) ((float4*)sm)[p4] = xc[p4];
    __syncthreads();
    int t = threadIdx.x;
    if (t < KB_H) {
        float s = 0.f;
        for (int j = 0; j < KB_W; j++) s += sm[t * KB_W + j];
        srow[t] = s;
        g_rowS[n * KB_H + t] = s;
    } else if (t < KB_H + KB_W) {
        int j = t - KB_H;
        float s = 0.f;
        for (int i = 0; i < KB_H; i++) s += sm[i * KB_W + j];
        scol[j] = s;
        g_colS[n * KB_W + j] = s;
    }
    __syncthreads();
    if (t == 0) {
        float tot = 0.f;
        for (int i = 0; i < KB_H; i++) tot += srow[i];
        for (int dy = 0; dy < 3; dy++)
            for (int dx = 0; dx < 3; dx++) {
                float s = tot;
                int ie = -1, je = -1;
                if (dy == 0) { s -= srow[KB_H - 1]; ie = KB_H - 1; }
                else if (dy == 2) { s -= srow[0]; ie = 0; }
                if (dx == 0) { s -= scol[KB_W - 1]; je = KB_W - 1; }
                else if (dx == 2) { s -= scol[0]; je = 0; }
                if (ie >= 0 && je >= 0) s += sm[ie * KB_W + je];
                g_S9[n * 9 + dy * 3 + dx] = s;
            }
    }
}

// ---- kB: 1x1 conv (32x32 over 112 positions) + sigmoid -> sh, sw ----
__global__ __launch_bounds__(128) void kB(const float* __restrict__ w1, const float* __restrict__ b1) {
    int bg = blockIdx.x;
    __shared__ float cat[KB_CG][112];
    __shared__ float w1s[KB_CG * KB_CG];
    int t = threadIdx.x;
    for (int m = t; m < KB_CG * KB_CG; m += 128) w1s[m] = w1[m];
    for (int m = t; m < KB_CG * 112; m += 128) {
        int cc = m / 112, u = m % 112;
        int n = bg * KB_CG + cc;
        cat[cc][u] = (u < KB_H) ? g_rowS[n * KB_H + u] * (1.0f / KB_W)
                                : g_colS[n * KB_W + (u - KB_H)] * (1.0f / KB_H);
    }
    __syncthreads();
    for (int m = t; m < KB_CG * 112; m += 128) {
        int o = m / 112, u = m % 112;
        float acc = b1[o];
        for (int i = 0; i < KB_CG; i++) acc += w1s[o * KB_CG + i] * cat[i][u];
        float s = sigm(acc);
        int n = bg * KB_CG + o;
        if (u < KB_H) g_sh[n * KB_H + u] = s;
        else g_sw[n * KB_W + (u - KB_H)] = s;
    }
}

// ---- kC: per-channel mean / mean-of-sq of x0 = x * sh * sw (float4) ----
__global__ __launch_bounds__(256) void kC(const float* __restrict__ x) {
    int n = blockIdx.x;
    __shared__ float shs[KB_H], sws[KB_W];
    __shared__ float red[16];
    int t = threadIdx.x;
    if (t < KB_H) shs[t] = g_sh[n * KB_H + t];
    else if (t < KB_H + KB_W) sws[t - KB_H] = g_sw[n * KB_W + (t - KB_H)];
    __syncthreads();
    const float4* xc = (const float4*)(x + (size_t)n * KB_P);
    float s = 0.f, s2 = 0.f;
    for (int p4 = t; p4 < KB_P / 4; p4 += 256) {
        int i = p4 / 14, j0 = (p4 % 14) * 4;
        float4 xv = xc[p4];
        float gi = shs[i];
        float v0 = xv.x * gi * sws[j0 + 0];
        float v1 = xv.y * gi * sws[j0 + 1];
        float v2 = xv.z * gi * sws[j0 + 2];
        float v3 = xv.w * gi * sws[j0 + 3];
        s += v0 + v1 + v2 + v3;
        s2 += v0 * v0 + v1 * v1 + v2 * v2 + v3 * v3;
    }
    s = warpSum(s);
    s2 = warpSum(s2);
    int wid = t >> 5, lane = t & 31;
    if (lane == 0) { red[wid] = s; red[8 + wid] = s2; }
    __syncthreads();
    if (t == 0) {
        float a = 0.f, b2 = 0.f;
        for (int k = 0; k < 8; k++) { a += red[k]; b2 += red[8 + k]; }
        g_mu[n] = a * (1.0f / KB_P);
        g_m2[n] = b2 * (1.0f / KB_P);
    }
}

// ---- kD1: per bg: x2mean from S9, x21 softmax, fold GN coeffs ----
__global__ __launch_bounds__(32) void kD1(const float* __restrict__ w3a, const float* __restrict__ b3a,
                                          const float* __restrict__ gnw, const float* __restrict__ gnb) {
    int bg = blockIdx.x;
    int c = threadIdx.x;
    __shared__ float S9s[KB_CG * 9];
    for (int m = c; m < KB_CG * 9; m += 32) S9s[m] = g_S9[bg * KB_CG * 9 + m];
    __syncwarp();
    float acc = 0.f;
    for (int m = 0; m < KB_CG * 9; m++) acc += w3a[c * KB_CG * 9 + m] * S9s[m];
    float x2m = acc * (1.0f / KB_P) + b3a[c];
    float mx = warpMax(x2m);
    float e = expf(x2m - mx);
    float ssum = warpSum(e);
    float x21 = e / ssum;
    int n = bg * KB_CG + c;
    float mu = g_mu[n];
    float var = g_m2[n] - mu * mu;
    if (var < 0.f) var = 0.f;
    float isig = rsqrtf(var + KB_EPS);
    g_w1c[n] = x21 * gnw[c] * isig;
    float part = x21 * (gnb[c] - gnw[c] * mu * isig);
    part = warpSum(part);
    if (c == 0) g_c1[bg] = part + g_cx11b;
}

// ---- kD2: per-channel batchnorm stats ----
__global__ __launch_bounds__(256) void kD2() {
    int c = threadIdx.x;
    float s = 0.f, s2 = 0.f;
    for (int b = 0; b < KB_B; b++) { s += g_mu[b * KB_C + c]; s2 += g_m2[b * KB_C + c]; }
    s *= (1.0f / KB_B);
    s2 *= (1.0f / KB_B);
    float bv = s2 - s * s;
    if (bv < 0.f) bv = 0.f;
    float isbn = rsqrtf(bv + KB_EPS);
    g_bm[c] = s;
    g_isbn[c] = isbn;
    g_alpha[c] = isbn * (1.0f / KB_C);
}

// ---- kE: fused channel sweep, halo-free conv via y9 shift-combine ----
// block: (tile, b), 576 threads; rows r=0..9 map to i = i0 + r - 1 (1-row halo)
__global__ __launch_bounds__(576) void kE(const float* __restrict__ x) {
    int tile = blockIdx.x, b = blockIdx.y;
    int i0 = tile * 8;
    __shared__ float wms[KB_C * 9];
    __shared__ float vfs[KB_CG * 9];
    __shared__ float als[KB_C];
    __shared__ float wcs[KB_C];
    __shared__ float shg[KB_CG * 10];
    __shared__ float swg[KB_CG * KB_W];
    __shared__ float ysm[9 * 580];   // [k][10 rows][58 cols padded]
    int t = threadIdx.x;
    for (int m = t; m < KB_C * 9; m += 576) wms[m] = g_wmean[m];
    for (int m = t; m < KB_CG * 9; m += 576) vfs[m] = g_veff[m];
    for (int m = t; m < KB_C; m += 576) { als[m] = g_alpha[m]; wcs[m] = g_w1c[b * KB_C + m]; }
    // zero padded columns of ysm (never overwritten)
    for (int m = t; m < 90; m += 576) {
        int k = m / 10, rr = m % 10;
        ysm[k * 580 + rr * 58] = 0.f;
        ysm[k * 580 + rr * 58 + 57] = 0.f;
    }
    int r = t / 56, j = t - r * 56;
    bool hasrow = (t < 560);
    int ig = i0 + r - 1;
    bool rowok = hasrow && (ig >= 0) && (ig < KB_H);
    bool inner = hasrow && (r >= 1) && (r <= 8);
    const float* xb = x + (size_t)b * KB_C * KB_P;
    float t3a = 0.f;
    float z[9];
#pragma unroll
    for (int k = 0; k < 9; k++) z[k] = 0.f;
    for (int g = 0; g < KB_G; g++) {
        __syncthreads();  // prev group's ysm reads + gate reads done
        // load gates for this group's 32 channels
        for (int m = t; m < KB_CG * 66; m += 576) {
            int c = m / 66, u = m - c * 66;
            int n = (b * KB_C + g * KB_CG + c);
            if (u < 10) {
                int gi = i0 + u - 1;
                shg[c * 10 + u] = (gi >= 0 && gi < KB_H) ? g_sh[n * KB_H + gi] : 0.f;
            } else {
                swg[c * KB_W + (u - 10)] = g_sw[n * KB_W + (u - 10)];
            }
        }
        __syncthreads();
        float wp = 0.f;
        float y[9];
#pragma unroll
        for (int k = 0; k < 9; k++) y[k] = 0.f;
#pragma unroll 4
        for (int cc = 0; cc < KB_CG; cc++) {
            int c = g * KB_CG + cc;
            float xv = rowok ? __ldg(xb + (size_t)c * KB_P + ig * KB_W + j) : 0.f;
#pragma unroll
            for (int k = 0; k < 9; k++) y[k] += vfs[cc * 9 + k] * xv;
            if (inner) {
#pragma unroll
                for (int k = 0; k < 9; k++) z[k] += wms[c * 9 + k] * xv;
                float x0 = xv * shg[cc * 10 + r] * swg[cc * KB_W + j];
                t3a += als[c] * x0;
                wp += wcs[c] * x0;
            }
        }
        if (hasrow) {
#pragma unroll
            for (int k = 0; k < 9; k++) ysm[k * 580 + r * 58 + j + 1] = y[k];
        }
        __syncthreads();
        if (inner) {
            float cp = 0.f;
#pragma unroll
            for (int dy = 0; dy < 3; dy++)
#pragma unroll
                for (int dx = 0; dx < 3; dx++)
                    cp += ysm[(dy * 3 + dx) * 580 + (r + dy - 1) * 58 + (j + dx)];
            int bg = b * KB_G + g;
            g_w1map[(size_t)bg * KB_P + ig * KB_W + j] = sigm(cp + wp + g_c1[bg]);
        }
    }
    if (inner) {
        int p = ig * KB_W + j;
        g_t3[b * KB_P + p] = t3a;
#pragma unroll
        for (int k = 0; k < 9; k++) g_z9[((size_t)(b * 9 + k)) * KB_P + p] = z[k];
    }
}

// ---- kSoft: fused pixel softmaxes: blocks 0..31 -> x31, 32..63 -> x41 ----
__global__ __launch_bounds__(512) void kSoft() {
    bool do41 = blockIdx.x >= KB_B;
    int b = do41 ? (blockIdx.x - KB_B) : blockIdx.x;
    __shared__ float buf[KB_P];
    __shared__ float red[17];
    int t = threadIdx.x;
    float lm = -3.4e38f;
    if (!do41) {
        for (int p = t; p < KB_P; p += 512) {
            float v = g_t3[b * KB_P + p];
            buf[p] = v;
            lm = fmaxf(lm, v);
        }
    } else {
        for (int p = t; p < KB_P; p += 512) {
            int i = p / KB_W, j = p - i * KB_W;
            float s = 0.f;
#pragma unroll
            for (int dy = 0; dy < 3; dy++) {
                int gi = i + dy - 1;
                if (gi < 0 || gi >= KB_H) continue;
#pragma unroll
                for (int dx = 0; dx < 3; dx++) {
                    int gj = j + dx - 1;
                    if (gj < 0 || gj >= KB_W) continue;
                    s += g_z9[((size_t)(b * 9 + dy * 3 + dx)) * KB_P + gi * KB_W + gj];
                }
            }
            buf[p] = s;
            lm = fmaxf(lm, s);
        }
    }
    lm = warpMax(lm);
    int wid = t >> 5, lane = t & 31;
    if (lane == 0) red[wid] = lm;
    __syncthreads();
    if (t < 32) {
        float v = (t < 16) ? red[t] : -3.4e38f;
        v = warpMax(v);
        if (t == 0) red[16] = v;
    }
    __syncthreads();
    float mx = red[16];
    float ls = 0.f;
    for (int p = t; p < KB_P; p += 512) {
        float e = expf(buf[p] - mx);
        buf[p] = e;
        ls += e;
    }
    ls = warpSum(ls);
    __syncthreads();
    if (lane == 0) red[wid] = ls;
    __syncthreads();
    if (t < 32) {
        float v = (t < 16) ? red[t] : 0.f;
        v = warpSum(v);
        if (t == 0) red[16] = v;
    }
    __syncthreads();
    float inv = 1.0f / red[16];
    float* dst = do41 ? g_x41 : g_x31;
    for (int p = t; p < KB_P; p += 512) dst[b * KB_P + p] = buf[p] * inv;
}

// ---- kF: per (b, 8-channel chunk): s1[c,k] and t41[c] ----
__global__ __launch_bounds__(256) void kF(const float* __restrict__ x) {
    int chunk = blockIdx.x, b = blockIdx.y;
    __shared__ float x31pad[58 * 58];
    __shared__ float x41s[KB_P];
    __shared__ float shs[8 * KB_H];
    __shared__ float sws[8 * KB_W];
    __shared__ float red[8 * 10];
    int t = threadIdx.x;
    for (int m = t; m < 58 * 58; m += 256) x31pad[m] = 0.f;
    __syncthreads();
    for (int p = t; p < KB_P; p += 256) {
        int i = p / KB_W, j = p - i * KB_W;
        x31pad[(i + 1) * 58 + (j + 1)] = g_x31[b * KB_P + p];
        x41s[p] = g_x41[b * KB_P + p];
    }
    for (int m = t; m < 8 * 112; m += 256) {
        int cc = m / 112, u = m % 112;
        int n = b * KB_C + chunk * 8 + cc;
        if (u < KB_H) shs[cc * KB_H + u] = g_sh[n * KB_H + u];
        else sws[cc * KB_W + (u - KB_H)] = g_sw[n * KB_W + (u - KB_H)];
    }
    __syncthreads();
    int wid = t >> 5, lane = t & 31;
    for (int cc = 0; cc < 8; cc++) {
        int n = b * KB_C + chunk * 8 + cc;
        const float4* xc = (const float4*)(x + (size_t)n * KB_P);
        float acc[9];
#pragma unroll
        for (int k = 0; k < 9; k++) acc[k] = 0.f;
        float t41 = 0.f;
        for (int p4 = t; p4 < KB_P / 4; p4 += 256) {
            int i = p4 / 14, j = (p4 % 14) * 4;
            float4 xv = xc[p4];
            float gi = shs[cc * KB_H + i];
            float g0 = gi * sws[cc * KB_W + j + 0];
            float g1 = gi * sws[cc * KB_W + j + 1];
            float g2 = gi * sws[cc * KB_W + j + 2];
            float g3 = gi * sws[cc * KB_W + j + 3];
            float4 w41 = *(const float4*)(x41s + p4 * 4);
            t41 += w41.x * xv.x * g0 + w41.y * xv.y * g1 + w41.z * xv.z * g2 + w41.w * xv.w * g3;
#pragma unroll
            for (int dy = 0; dy < 3; dy++) {
                const float* rp = x31pad + (i + 2 - dy) * 58 + j;
                float v0 = rp[0], v1 = rp[1], v2 = rp[2], v3 = rp[3], v4 = rp[4], v5 = rp[5];
                acc[dy * 3 + 0] += v2 * xv.x + v3 * xv.y + v4 * xv.z + v5 * xv.w;
                acc[dy * 3 + 1] += v1 * xv.x + v2 * xv.y + v3 * xv.z + v4 * xv.w;
                acc[dy * 3 + 2] += v0 * xv.x + v1 * xv.y + v2 * xv.z + v3 * xv.w;
            }
        }
#pragma unroll
        for (int k = 0; k < 9; k++) {
            acc[k] = warpSum(acc[k]);
            if (lane == 0) red[wid * 10 + k] = acc[k];
        }
        t41 = warpSum(t41);
        if (lane == 0) red[wid * 10 + 9] = t41;
        __syncthreads();
        if (t < 10) {
            float s = 0.f;
            for (int w = 0; w < 8; w++) s += red[w * 10 + t];
            if (t < 9) g_s1[n * 9 + t] = s;
            else g_t41[n] = s;
        }
        __syncthreads();
    }
}

// ---- kW2: weights2 = w3b . s1 + b3b + isbn*(t41 - bm); sigmoid ----
__global__ __launch_bounds__(256) void kW2(const float* __restrict__ w3b, const float* __restrict__ b3b) {
    int b = blockIdx.x >> 3;
    int chunk = blockIdx.x & 7;  // 32 out-channels per block
    __shared__ float s1s[KB_C * 9];
    int t = threadIdx.x;
    for (int m = t; m < KB_C * 9; m += 256) s1s[m] = g_s1[b * KB_C * 9 + m];
    __syncthreads();
    int wid = t >> 5, lane = t & 31;
    for (int q = 0; q < 4; q++) {
        int c = chunk * 32 + wid * 4 + q;
        float a = 0.f;
        const float* wr = w3b + (size_t)c * (KB_C * 9);
        for (int m = lane; m < KB_C * 9; m += 32) a += wr[m] * s1s[m];
        a = warpSum(a);
        if (lane == 0) {
            float w2 = a + b3b[c] + g_isbn[c] * (g_t41[b * KB_C + c] - g_bm[c]);
            g_w2sig[b * KB_C + c] = sigm(w2);
        }
    }
}

// ---- kFinal: out = x * (sigmoid(w1map) + sigmoid(w2)) ----
__global__ __launch_bounds__(256) void kFinal(const float* __restrict__ x, float* __restrict__ out) {
    size_t e = (size_t)blockIdx.x * 256 + threadIdx.x;
    const size_t total = (size_t)KB_B * KB_C * (KB_P / 4);
    if (e >= total) return;
    int n = (int)(e / (KB_P / 4));
    int p4 = (int)(e % (KB_P / 4));
    int bg = n >> 5;
    float4 xv = ((const float4*)x)[e];
    float4 wm = ((const float4*)g_w1map)[(size_t)bg * (KB_P / 4) + p4];
    float w2 = g_w2sig[n];
    float4 o;
    o.x = xv.x * (wm.x + w2);
    o.y = xv.y * (wm.y + w2);
    o.z = xv.z * (wm.z + w2);
    o.w = xv.w * (wm.w + w2);
    ((float4*)out)[e] = o;
}

extern "C" void kernel_launch(void* const* d_in, const int* in_sizes, int n_in,
                              void* d_out, int out_size) {
    const float* x   = (const float*)d_in[0];
    const float* w1  = (const float*)d_in[1];
    const float* b1  = (const float*)d_in[2];
    const float* w3a = (const float*)d_in[3];
    const float* b3a = (const float*)d_in[4];
    const float* w3b = (const float*)d_in[5];
    const float* b3b = (const float*)d_in[6];
    const float* gnw = (const float*)d_in[7];
    const float* gnb = (const float*)d_in[8];
    float* out = (float*)d_out;

    kPrepW<<<9, 256>>>(w3b);
    kPrepV<<<1, 288>>>(w3a, b3a, gnb);
    kA<<<KB_NCH, 256>>>(x);
    kB<<<KB_BG, 128>>>(w1, b1);
    kC<<<KB_NCH, 256>>>(x);
    kD1<<<KB_BG, 32>>>(w3a, b3a, gnw, gnb);
    kD2<<<1, 256>>>();
    kE<<<dim3(7, KB_B), 576>>>(x);
    kSoft<<<2 * KB_B, 512>>>();
    kF<<<dim3(32, KB_B), 256>>>(x);
    kW2<<<KB_BG, 256>>>(w3b, b3b);
    size_t total4 = (size_t)KB_B * KB_C * (KB_P / 4);
    kFinal<<<(unsigned)((total4 + 255) / 256), 256>>>(x, out);
}